// round 1
// baseline (speedup 1.0000x reference)
#include <cuda_runtime.h>
#include <math.h>

#define BB 8
#define DD 256
#define NL 10000
#define KN 32
#define KC 10032
#define NS 100

// scratch (no allocations allowed)
__device__ float g_logits[BB * KC];
__device__ float g_boot[NS * BB * DD];

// ---------- block reductions (256 threads) ----------
__device__ __forceinline__ float blockMax(float v, float* red) {
#pragma unroll
    for (int o = 16; o; o >>= 1) v = fmaxf(v, __shfl_xor_sync(0xffffffffu, v, o));
    int wid = threadIdx.x >> 5;
    if ((threadIdx.x & 31) == 0) red[wid] = v;
    __syncthreads();
    if (threadIdx.x < 32) {
        float x = (threadIdx.x < 8) ? red[threadIdx.x] : -INFINITY;
#pragma unroll
        for (int o = 4; o; o >>= 1) x = fmaxf(x, __shfl_xor_sync(0xffffffffu, x, o));
        if (threadIdx.x == 0) red[0] = x;
    }
    __syncthreads();
    v = red[0];
    __syncthreads();
    return v;
}

__device__ __forceinline__ float blockSum(float v, float* red) {
#pragma unroll
    for (int o = 16; o; o >>= 1) v += __shfl_xor_sync(0xffffffffu, v, o);
    int wid = threadIdx.x >> 5;
    if ((threadIdx.x & 31) == 0) red[wid] = v;
    __syncthreads();
    if (threadIdx.x < 32) {
        float x = (threadIdx.x < 8) ? red[threadIdx.x] : 0.f;
#pragma unroll
        for (int o = 4; o; o >>= 1) x += __shfl_xor_sync(0xffffffffu, x, o);
        if (threadIdx.x == 0) red[0] = x;
    }
    __syncthreads();
    v = red[0];
    __syncthreads();
    return v;
}

// ---------- kernel 1: logits[b,k] ----------
// live: live_ll - 0.5*||x - xt||^2 / ts^2 - log(ts); new: ll (exact cancellation)
__global__ void k_logits(const float* __restrict__ xt,
                         const float* __restrict__ live_x0,
                         const float* __restrict__ live_ll,
                         const float* __restrict__ x0,
                         const float* __restrict__ ll,
                         const float* __restrict__ tsp) {
    int gw = (blockIdx.x * blockDim.x + threadIdx.x) >> 5;
    int lane = threadIdx.x & 31;
    if (gw >= BB * KC) return;
    int b = gw / KC;
    int k = gw - b * KC;
    if (k >= NL) {
        if (lane == 0) g_logits[gw] = ll[b * KN + (k - NL)];
        return;
    }
    const float4* xr  = (const float4*)(live_x0 + ((size_t)b * NL + k) * DD);
    const float4* xtr = (const float4*)(xt + (size_t)b * DD);
    float s = 0.f;
#pragma unroll
    for (int i = 0; i < 2; i++) {
        float4 a = xr[lane + i * 32];
        float4 c = xtr[lane + i * 32];
        float d0 = a.x - c.x, d1 = a.y - c.y, d2 = a.z - c.z, d3 = a.w - c.w;
        s += d0 * d0 + d1 * d1 + d2 * d2 + d3 * d3;
    }
#pragma unroll
    for (int o = 16; o; o >>= 1) s += __shfl_xor_sync(0xffffffffu, s, o);
    if (lane == 0) {
        float ts = *tsp;
        g_logits[gw] = live_ll[(size_t)b * NL + k] - 0.5f * s / (ts * ts) - logf(ts);
    }
}

// ---------- kernel 2: final score (one CTA per b) ----------
__global__ void k_score(const float* __restrict__ xt,
                        const float* __restrict__ live_x0,
                        const float* __restrict__ x0,
                        const float* __restrict__ tsp,
                        float* __restrict__ out) {
    extern __shared__ int sm[];
    int*   list = sm;                 // KC ints
    float* w    = (float*)(sm + KC);  // KC floats
    __shared__ float red[8];
    __shared__ int nact;
    int b = blockIdx.x, t = threadIdx.x;
    float ts = *tsp;
    const float* L = g_logits + (size_t)b * KC;

    float m = -INFINITY;
    for (int k = t; k < KC; k += DD) m = fmaxf(m, L[k]);
    m = blockMax(m, red);

    float z = 0.f;
    for (int k = t; k < KC; k += DD) {
        float e = expf(L[k] - m);
        w[k] = e;
        z += e;
    }
    z = blockSum(z, red);

    if (t == 0) nact = 0;
    __syncthreads();
    for (int k = t; k < KC; k += DD)
        if (w[k] > 0.f) { int p = atomicAdd(&nact, 1); list[p] = k; }
    __syncthreads();

    int na = nact;
    float acc = 0.f;
    for (int j = 0; j < na; j++) {
        int k = list[j];
        const float* row = (k < NL) ? (live_x0 + ((size_t)b * NL + k) * DD)
                                    : (x0 + ((size_t)b * KN + (k - NL)) * DD);
        acc = fmaf(w[k], row[t], acc);
    }
    out[(size_t)b * DD + t] = acc / (z * ts) - xt[(size_t)b * DD + t] / ts;
}

// ---------- kernel 3: bootstrap samples (grid = [NS, B]) ----------
__global__ void k_boot(const float* __restrict__ xt,
                       const float* __restrict__ live_x0,
                       const float* __restrict__ x0,
                       const int* __restrict__ bidx,
                       const float* __restrict__ tsp) {
    extern __shared__ int sm[];
    int*   cnt = sm;                 // KC counts, later reused as compacted list
    float* w   = (float*)(sm + KC);  // KC weights
    __shared__ float red[8];
    __shared__ int nact;
    int n = blockIdx.x, b = blockIdx.y, t = threadIdx.x;
    float ts = *tsp;
    const float* L = g_logits + (size_t)b * KC;
    const int* idx = bidx + ((size_t)n * BB + b) * KC;

    for (int k = t; k < KC; k += DD) cnt[k] = 0;
    __syncthreads();
    for (int i = t; i < KC; i += DD) atomicAdd(&cnt[idx[i]], 1);
    __syncthreads();

    float m = -INFINITY;
    for (int k = t; k < KC; k += DD)
        if (cnt[k]) m = fmaxf(m, L[k]);
    m = blockMax(m, red);

    float z = 0.f;
    for (int k = t; k < KC; k += DD) {
        int c = cnt[k];
        float e = c ? (float)c * expf(L[k] - m) : 0.f;
        w[k] = e;
        z += e;
    }
    z = blockSum(z, red);

    if (t == 0) nact = 0;
    __syncthreads();
    for (int k = t; k < KC; k += DD)
        if (w[k] > 0.f) { int p = atomicAdd(&nact, 1); cnt[p] = k; }  // reuse cnt as list
    __syncthreads();

    int na = nact;
    float acc = 0.f;
    for (int j = 0; j < na; j++) {
        int k = cnt[j];
        const float* row = (k < NL) ? (live_x0 + ((size_t)b * NL + k) * DD)
                                    : (x0 + ((size_t)b * KN + (k - NL)) * DD);
        acc = fmaf(w[k], row[t], acc);
    }
    g_boot[((size_t)n * BB + b) * DD + t] = acc / (z * ts) - xt[(size_t)b * DD + t] / ts;
}

// ---------- kernel 4: std (ddof=1) + converged ----------
__global__ void k_conv(const float* __restrict__ tsp, float* __restrict__ out, int out_size) {
    int b = blockIdx.x, d = threadIdx.x;
    float ts = *tsp;
    float s = 0.f;
    for (int n = 0; n < NS; n++) s += g_boot[((size_t)n * BB + b) * DD + d];
    float mean = s * (1.f / NS);
    float v = 0.f;
    for (int n = 0; n < NS; n++) {
        float x = g_boot[((size_t)n * BB + b) * DD + d] - mean;
        v = fmaf(x, x, v);
    }
    float sigma = sqrtf(v * (1.f / (NS - 1)));
    int ok = sigma < 0.1f * ts;
    int all = __syncthreads_and(ok);
    if (d == 0 && out_size >= BB * DD + BB) out[BB * DD + b] = all ? 1.f : 0.f;
}

extern "C" void kernel_launch(void* const* d_in, const int* in_sizes, int n_in,
                              void* d_out, int out_size) {
    const float* xt      = (const float*)d_in[0];
    const float* live_x0 = (const float*)d_in[1];
    const float* live_ll = (const float*)d_in[2];
    const float* x0      = (const float*)d_in[3];
    const float* ll      = (const float*)d_in[4];
    const float* tsp     = (const float*)d_in[5];
    const int*   bidx    = (const int*)d_in[6];
    float* out = (float*)d_out;

    const int smem = KC * 8;  // 80256 bytes: counts/list + weights
    cudaFuncSetAttribute(k_score, cudaFuncAttributeMaxDynamicSharedMemorySize, smem);
    cudaFuncSetAttribute(k_boot,  cudaFuncAttributeMaxDynamicSharedMemorySize, smem);

    // 1 warp per (b,k) row: 8*10032 = 80256 warps -> 10032 CTAs of 256 threads
    k_logits<<<(BB * KC + 7) / 8, 256>>>(xt, live_x0, live_ll, x0, ll, tsp);

    k_score<<<BB, 256, smem>>>(xt, live_x0, x0, tsp, out);

    dim3 g3(NS, BB);
    k_boot<<<g3, 256, smem>>>(xt, live_x0, x0, bidx, tsp);

    k_conv<<<BB, 256>>>(tsp, out, out_size);
}